// round 9
// baseline (speedup 1.0000x reference)
#include <cuda_runtime.h>
#include <cuda_bf16.h>
#include <math.h>

// Problem constants
#define Bsz   2
#define Npts  8192
#define Kn    3
#define NQ    (Bsz * Npts)

// Spatial grid
#define GRD   48
#define NC3   (GRD * GRD * GRD)       // 110592 cells
#define CS    0.25f                   // cell size
#define INVCS 4.0f
#define ORG   (-6.0f)                 // grid origin (covers N(0,1) with huge margin)

// Device scratch (static — no allocations)
__device__ int    g_cnt[Bsz * NC3];
__device__ int    g_off[Bsz * (NC3 + 1)];
__device__ int    g_cur[Bsz * NC3];
__device__ float4 g_pts[NQ];          // sorted {-2x,-2y,-2z,|s|^2}
__device__ int    g_sidx[NQ];         // sorted -> original local index
__device__ int    g_nn[NQ * 3];       // per ORIGINAL query: 3 neighbor orig indices
__device__ float  g_dsum[NQ];         // per ORIGINAL query: d0+d1+d2

__device__ __forceinline__ int clampi(int v, int lo, int hi) {
    return v < lo ? lo : (v > hi ? hi : v);
}
__device__ __forceinline__ void cell_coords(float x, float y, float z,
                                            int& ci, int& cj, int& ck) {
    ci = clampi((int)floorf((x - ORG) * INVCS), 0, GRD - 1);
    cj = clampi((int)floorf((y - ORG) * INVCS), 0, GRD - 1);
    ck = clampi((int)floorf((z - ORG) * INVCS), 0, GRD - 1);
}

// ---------------------------------------------------------------------------
__global__ void zero_kernel(float* out) {
    const int t = blockIdx.x * blockDim.x + threadIdx.x;
    if (t < Bsz * NC3) g_cnt[t] = 0;
    if (t == 0) out[0] = 0.0f;
}

__global__ void count_kernel(const float* __restrict__ xyz) {
    const int t = blockIdx.x * blockDim.x + threadIdx.x;
    if (t >= NQ) return;
    const int b = t >> 13, p = t & (Npts - 1);
    const float* xp = xyz + ((size_t)b * Npts + p) * 3;
    int ci, cj, ck;
    cell_coords(xp[0], xp[1], xp[2], ci, cj, ck);
    atomicAdd(&g_cnt[b * NC3 + (ci * GRD + cj) * GRD + ck], 1);
}

// One block per batch; 1024 threads; SPAN=108 cells per thread.
__global__ __launch_bounds__(1024) void scan_kernel() {
    const int b   = blockIdx.x;
    const int tid = threadIdx.x;
    const int SPAN = NC3 / 1024;      // 108
    const int base = b * NC3 + tid * SPAN;

    int s = 0;
    for (int i = 0; i < SPAN; i++) s += g_cnt[base + i];

    __shared__ int sm[1024];
    sm[tid] = s;
    __syncthreads();
    // Hillis-Steele inclusive scan (double-sync)
    for (int d = 1; d < 1024; d <<= 1) {
        int v = (tid >= d) ? sm[tid - d] : 0;
        __syncthreads();
        sm[tid] += v;
        __syncthreads();
    }
    int run = sm[tid] - s;            // exclusive prefix of this thread's span

    const int obase = b * (NC3 + 1) + tid * SPAN;
    for (int i = 0; i < SPAN; i++) {
        const int c = g_cnt[base + i];
        g_off[obase + i] = run;
        g_cur[base + i]  = run;
        run += c;
    }
    if (tid == 1023) g_off[b * (NC3 + 1) + NC3] = run;   // == Npts
}

__global__ void scatter_kernel(const float* __restrict__ xyz) {
    const int t = blockIdx.x * blockDim.x + threadIdx.x;
    if (t >= NQ) return;
    const int b = t >> 13, p = t & (Npts - 1);
    const float* xp = xyz + ((size_t)b * Npts + p) * 3;
    const float x = xp[0], y = xp[1], z = xp[2];
    int ci, cj, ck;
    cell_coords(x, y, z, ci, cj, ck);
    const int pos = atomicAdd(&g_cur[b * NC3 + (ci * GRD + cj) * GRD + ck], 1);
    const float n = fmaf(x, x, fmaf(y, y, z * z));
    g_pts[(b << 13) + pos]  = make_float4(-2.0f * x, -2.0f * y, -2.0f * z, n);
    g_sidx[(b << 13) + pos] = p;
}

// ---------------------------------------------------------------------------
// Exact KNN: thread per sorted slot. Ring search over Chebyshev shells with
// stop bound: after shells 0..r, all unexplored cells are >= r*CS away.
// t-space distances, bit-identical fma chain to the R8 passing kernel.
// ---------------------------------------------------------------------------
__global__ __launch_bounds__(128) void knn_kernel() {
    const int j = blockIdx.x * blockDim.x + threadIdx.x;
    if (j >= NQ) return;
    const int b  = j >> 13;
    const int pb = b << 13;
    const int ob = b * (NC3 + 1);

    const float4 q4 = g_pts[j];
    const float qx = -0.5f * q4.x;
    const float qy = -0.5f * q4.y;
    const float qz = -0.5f * q4.z;
    const float qn = q4.w;

    int qi, qj, qk;
    cell_coords(qx, qy, qz, qi, qj, qk);

    float t0 = INFINITY, t1 = INFINITY, t2 = INFINITY;
    int   n0 = 0, n1 = 0, n2 = 0;

    for (int r = 0; r < GRD; r++) {
        const int ilo = qi - r < 0 ? 0 : qi - r;
        const int ihi = qi + r > GRD - 1 ? GRD - 1 : qi + r;
        const int jlo = qj - r < 0 ? 0 : qj - r;
        const int jhi = qj + r > GRD - 1 ? GRD - 1 : qj + r;
        const int klo = qk - r < 0 ? 0 : qk - r;
        const int khi = qk + r > GRD - 1 ? GRD - 1 : qk + r;

        for (int ci = ilo; ci <= ihi; ci++) {
            const int adi = abs(ci - qi);
            for (int cj = jlo; cj <= jhi; cj++) {
                const bool faceij = (adi == r) || (abs(cj - qj) == r);
                const int rowb = ob + (ci * GRD + cj) * GRD;
                for (int ck = klo; ck <= khi; ck++) {
                    if (!faceij && abs(ck - qk) != r) continue;  // shell only
                    const int cc = rowb + ck;
                    const int s  = g_off[cc];
                    const int e  = g_off[cc + 1];
                    for (int p = s; p < e; p++) {
                        const float4 c4 = g_pts[pb + p];
                        float t = fmaf(qx, c4.x, c4.w);
                        t = fmaf(qy, c4.y, t);
                        t = fmaf(qz, c4.z, t);
                        if (t < t2) {
                            const int oi = g_sidx[pb + p];
                            if (t < t0)      { t2 = t1; n2 = n1; t1 = t0; n1 = n0; t0 = t; n0 = oi; }
                            else if (t < t1) { t2 = t1; n2 = n1; t1 = t;  n1 = oi; }
                            else             { t2 = t;  n2 = oi; }
                        }
                    }
                }
            }
        }
        // Stop: every unexplored cell is >= r*CS away from q.
        float bound = (float)r * CS;
        bound *= bound;
        if (t2 + qn <= bound * 0.9999f) break;
    }

    const int orig = g_sidx[j];
    const int gq   = pb + orig;
    g_nn[gq * 3 + 0] = n0;
    g_nn[gq * 3 + 1] = n1;
    g_nn[gq * 3 + 2] = n2;
    g_dsum[gq] = (t0 + qn) + (t1 + qn) + (t2 + qn);
}

// ---------------------------------------------------------------------------
// Loss: warp per query (proven R8 structure), reads g_nn / g_dsum.
// ---------------------------------------------------------------------------
#define K2_THREADS 256
#define K2_WARPS   (K2_THREADS / 32)

__global__ __launch_bounds__(K2_THREADS) void loss_kernel(
    const float* __restrict__ rot,  // [B,N,4]
    const float* __restrict__ scl,  // [B,N,3]
    const float* __restrict__ col,  // [B,N,45]
    const float* __restrict__ opa,  // [B,N,1]
    float* __restrict__ out)
{
    const int lane = threadIdx.x & 31;
    const int wid  = threadIdx.x >> 5;
    const int gq   = blockIdx.x * K2_WARPS + wid;
    const int b    = gq >> 13;

    const int r0 = b * Npts + g_nn[gq * 3 + 0];
    const int r1 = b * Npts + g_nn[gq * 3 + 1];
    const int r2 = b * Npts + g_nn[gq * 3 + 2];

    float local = 0.0f;
    if (lane == 0)
        local += g_dsum[gq] * (1.0f / ((float)Bsz * Npts * Kn));

    // 53 channels: 0..3 rot(C=4), 4..6 scales(C=3), 7 opacity(C=1), 8..52 colors(C=45)
    for (int c = lane; c < 53; c += 32) {
        const float* bp; int C; int cc;
        if (c < 4)       { bp = rot; C = 4;  cc = c;     }
        else if (c < 7)  { bp = scl; C = 3;  cc = c - 4; }
        else if (c < 8)  { bp = opa; C = 1;  cc = 0;     }
        else             { bp = col; C = 45; cc = c - 8; }

        const float x0 = __ldg(bp + (size_t)r0 * C + cc);
        const float x1 = __ldg(bp + (size_t)r1 * C + cc);
        const float x2 = __ldg(bp + (size_t)r2 * C + cc);

        const float m  = (x0 + x1 + x2) * (1.0f / 3.0f);
        const float e0 = x0 - m, e1 = x1 - m, e2 = x2 - m;
        const float var = fmaf(e0, e0, fmaf(e1, e1, e2 * e2)) * 0.5f;  // ddof=1
        local += sqrtf(var) * (1.0f / ((float)Bsz * Npts * (float)C));
    }

    #pragma unroll
    for (int off = 16; off > 0; off >>= 1)
        local += __shfl_xor_sync(0xffffffffu, local, off);

    __shared__ float red[K2_WARPS];
    if (lane == 0) red[wid] = local;
    __syncthreads();

    if (threadIdx.x < K2_WARPS) {
        float s = red[threadIdx.x];
        #pragma unroll
        for (int off = K2_WARPS / 2; off > 0; off >>= 1)
            s += __shfl_xor_sync((1u << K2_WARPS) - 1u, s, off);
        if (threadIdx.x == 0) atomicAdd(out, s);
    }
}

// ---------------------------------------------------------------------------
extern "C" void kernel_launch(void* const* d_in, const int* in_sizes, int n_in,
                              void* d_out, int out_size)
{
    const float* xyz = (const float*)d_in[0];
    const float* rot = (const float*)d_in[1];
    const float* scl = (const float*)d_in[2];
    const float* col = (const float*)d_in[3];
    const float* opa = (const float*)d_in[4];
    float* out = (float*)d_out;

    zero_kernel<<<(Bsz * NC3 + 255) / 256, 256>>>(out);
    count_kernel<<<NQ / 256, 256>>>(xyz);
    scan_kernel<<<Bsz, 1024>>>();
    scatter_kernel<<<NQ / 256, 256>>>(xyz);
    knn_kernel<<<NQ / 128, 128>>>();
    loss_kernel<<<NQ / K2_WARPS, K2_THREADS>>>(rot, scl, col, opa, out);
}

// round 10
// speedup vs baseline: 4.8629x; 4.8629x over previous
#include <cuda_runtime.h>
#include <cuda_bf16.h>
#include <math.h>

// Problem constants
#define Bsz   2
#define Npts  8192
#define Kn    3
#define NQ    (Bsz * Npts)

// Spatial grid: [-6,6]^3, cell 0.5 -> 24^3 cells, ~65 pts/cell at center
#define GRD   24
#define NC3   (GRD * GRD * GRD)       // 13824 cells
#define CS    0.5f
#define INVCS 2.0f
#define ORG   (-6.0f)

// Device scratch (static — no allocations)
__device__ int    g_cnt[Bsz * NC3];
__device__ int    g_off[Bsz * (NC3 + 1)];
__device__ int    g_cur[Bsz * NC3];
__device__ float4 g_pts[NQ];          // sorted {-2x,-2y,-2z,|s|^2}
__device__ int    g_sidx[NQ];         // sorted -> original local index
__device__ int    g_nn[NQ * 3];       // per ORIGINAL query: 3 neighbor orig indices
__device__ float  g_dsum[NQ];         // per ORIGINAL query: d0+d1+d2

__device__ __forceinline__ int clampi(int v, int lo, int hi) {
    return v < lo ? lo : (v > hi ? hi : v);
}
__device__ __forceinline__ void cell_coords(float x, float y, float z,
                                            int& ci, int& cj, int& ck) {
    ci = clampi((int)floorf((x - ORG) * INVCS), 0, GRD - 1);
    cj = clampi((int)floorf((y - ORG) * INVCS), 0, GRD - 1);
    ck = clampi((int)floorf((z - ORG) * INVCS), 0, GRD - 1);
}

// ---------------------------------------------------------------------------
__global__ void zero_kernel(float* out) {
    const int t = blockIdx.x * blockDim.x + threadIdx.x;
    if (t < Bsz * NC3) g_cnt[t] = 0;
    if (t == 0) out[0] = 0.0f;
}

__global__ void count_kernel(const float* __restrict__ xyz) {
    const int t = blockIdx.x * blockDim.x + threadIdx.x;
    if (t >= NQ) return;
    const int b = t >> 13, p = t & (Npts - 1);
    const float* xp = xyz + ((size_t)b * Npts + p) * 3;
    int ci, cj, ck;
    cell_coords(xp[0], xp[1], xp[2], ci, cj, ck);
    atomicAdd(&g_cnt[b * NC3 + (ci * GRD + cj) * GRD + ck], 1);
}

// One block per batch; 512 threads; SPAN=27 cells per thread (512*27=13824).
#define SCAN_T 512
__global__ __launch_bounds__(SCAN_T) void scan_kernel() {
    const int b   = blockIdx.x;
    const int tid = threadIdx.x;
    const int SPAN = NC3 / SCAN_T;    // 27
    const int base = b * NC3 + tid * SPAN;

    int s = 0;
    for (int i = 0; i < SPAN; i++) s += g_cnt[base + i];

    __shared__ int sm[SCAN_T];
    sm[tid] = s;
    __syncthreads();
    for (int d = 1; d < SCAN_T; d <<= 1) {
        int v = (tid >= d) ? sm[tid - d] : 0;
        __syncthreads();
        sm[tid] += v;
        __syncthreads();
    }
    int run = sm[tid] - s;            // exclusive prefix of this thread's span

    const int obase = b * (NC3 + 1) + tid * SPAN;
    for (int i = 0; i < SPAN; i++) {
        const int c = g_cnt[base + i];
        g_off[obase + i] = run;
        g_cur[base + i]  = run;
        run += c;
    }
    if (tid == SCAN_T - 1) g_off[b * (NC3 + 1) + NC3] = run;   // == Npts
}

__global__ void scatter_kernel(const float* __restrict__ xyz) {
    const int t = blockIdx.x * blockDim.x + threadIdx.x;
    if (t >= NQ) return;
    const int b = t >> 13, p = t & (Npts - 1);
    const float* xp = xyz + ((size_t)b * Npts + p) * 3;
    const float x = xp[0], y = xp[1], z = xp[2];
    int ci, cj, ck;
    cell_coords(x, y, z, ci, cj, ck);
    const int pos = atomicAdd(&g_cur[b * NC3 + (ci * GRD + cj) * GRD + ck], 1);
    const float n = fmaf(x, x, fmaf(y, y, z * z));
    g_pts[(b << 13) + pos]  = make_float4(-2.0f * x, -2.0f * y, -2.0f * z, n);
    g_sidx[(b << 13) + pos] = p;
}

// ---------------------------------------------------------------------------
// Exact KNN: thread per sorted slot (adjacent threads share cells -> coherent
// loads). Chebyshev shells; stop when every unexplored cell is >= r*CS away:
// after shells 0..r, unexplored cells have index distance >= r+1, so gap from
// q (inside its own cell) >= r*CS. t-space distance chain identical to R8/R9.
// ---------------------------------------------------------------------------
__global__ __launch_bounds__(128) void knn_kernel() {
    const int j = blockIdx.x * blockDim.x + threadIdx.x;
    if (j >= NQ) return;
    const int b  = j >> 13;
    const int pb = b << 13;
    const int ob = b * (NC3 + 1);

    const float4 q4 = g_pts[j];
    const float qx = -0.5f * q4.x;
    const float qy = -0.5f * q4.y;
    const float qz = -0.5f * q4.z;
    const float qn = q4.w;

    int qi, qj, qk;
    cell_coords(qx, qy, qz, qi, qj, qk);

    float t0 = INFINITY, t1 = INFINITY, t2 = INFINITY;
    int   n0 = 0, n1 = 0, n2 = 0;

    for (int r = 0; r < GRD; r++) {
        const int ilo = qi - r < 0 ? 0 : qi - r;
        const int ihi = qi + r > GRD - 1 ? GRD - 1 : qi + r;
        const int jlo = qj - r < 0 ? 0 : qj - r;
        const int jhi = qj + r > GRD - 1 ? GRD - 1 : qj + r;
        const int klo = qk - r < 0 ? 0 : qk - r;
        const int khi = qk + r > GRD - 1 ? GRD - 1 : qk + r;

        for (int ci = ilo; ci <= ihi; ci++) {
            const int adi = abs(ci - qi);
            for (int cj = jlo; cj <= jhi; cj++) {
                const bool faceij = (adi == r) || (abs(cj - qj) == r);
                const int rowb = ob + (ci * GRD + cj) * GRD;
                // shell-only in k unless on an i/j face
                int k0 = klo, k1 = khi, kstep = 1;
                for (int ck = k0; ck <= k1; ck += kstep) {
                    if (!faceij && abs(ck - qk) != r) continue;
                    const int cc = rowb + ck;
                    const int s  = g_off[cc];
                    const int e  = g_off[cc + 1];
                    for (int p = s; p < e; p++) {
                        const float4 c4 = g_pts[pb + p];
                        float t = fmaf(qx, c4.x, c4.w);
                        t = fmaf(qy, c4.y, t);
                        t = fmaf(qz, c4.z, t);
                        if (t < t2) {
                            const int oi = g_sidx[pb + p];
                            if (t < t0)      { t2 = t1; n2 = n1; t1 = t0; n1 = n0; t0 = t; n0 = oi; }
                            else if (t < t1) { t2 = t1; n2 = n1; t1 = t;  n1 = oi; }
                            else             { t2 = t;  n2 = oi; }
                        }
                    }
                }
            }
        }
        // Stop: every unexplored cell is >= r*CS away from q.
        float bound = (float)r * CS;
        bound *= bound;
        if (t2 + qn <= bound * 0.9999f) break;
    }

    const int orig = g_sidx[j];
    const int gq   = pb + orig;
    g_nn[gq * 3 + 0] = n0;
    g_nn[gq * 3 + 1] = n1;
    g_nn[gq * 3 + 2] = n2;
    g_dsum[gq] = (t0 + qn) + (t1 + qn) + (t2 + qn);
}

// ---------------------------------------------------------------------------
// Loss: warp per query (proven structure), reads g_nn / g_dsum.
// ---------------------------------------------------------------------------
#define K2_THREADS 256
#define K2_WARPS   (K2_THREADS / 32)

__global__ __launch_bounds__(K2_THREADS) void loss_kernel(
    const float* __restrict__ rot,  // [B,N,4]
    const float* __restrict__ scl,  // [B,N,3]
    const float* __restrict__ col,  // [B,N,45]
    const float* __restrict__ opa,  // [B,N,1]
    float* __restrict__ out)
{
    const int lane = threadIdx.x & 31;
    const int wid  = threadIdx.x >> 5;
    const int gq   = blockIdx.x * K2_WARPS + wid;
    const int b    = gq >> 13;

    const int r0 = b * Npts + g_nn[gq * 3 + 0];
    const int r1 = b * Npts + g_nn[gq * 3 + 1];
    const int r2 = b * Npts + g_nn[gq * 3 + 2];

    float local = 0.0f;
    if (lane == 0)
        local += g_dsum[gq] * (1.0f / ((float)Bsz * Npts * Kn));

    // 53 channels: 0..3 rot(C=4), 4..6 scales(C=3), 7 opacity(C=1), 8..52 colors(C=45)
    for (int c = lane; c < 53; c += 32) {
        const float* bp; int C; int cc;
        if (c < 4)       { bp = rot; C = 4;  cc = c;     }
        else if (c < 7)  { bp = scl; C = 3;  cc = c - 4; }
        else if (c < 8)  { bp = opa; C = 1;  cc = 0;     }
        else             { bp = col; C = 45; cc = c - 8; }

        const float x0 = __ldg(bp + (size_t)r0 * C + cc);
        const float x1 = __ldg(bp + (size_t)r1 * C + cc);
        const float x2 = __ldg(bp + (size_t)r2 * C + cc);

        const float m  = (x0 + x1 + x2) * (1.0f / 3.0f);
        const float e0 = x0 - m, e1 = x1 - m, e2 = x2 - m;
        const float var = fmaf(e0, e0, fmaf(e1, e1, e2 * e2)) * 0.5f;  // ddof=1
        local += sqrtf(var) * (1.0f / ((float)Bsz * Npts * (float)C));
    }

    #pragma unroll
    for (int off = 16; off > 0; off >>= 1)
        local += __shfl_xor_sync(0xffffffffu, local, off);

    __shared__ float red[K2_WARPS];
    if (lane == 0) red[wid] = local;
    __syncthreads();

    if (threadIdx.x < K2_WARPS) {
        float s = red[threadIdx.x];
        #pragma unroll
        for (int off = K2_WARPS / 2; off > 0; off >>= 1)
            s += __shfl_xor_sync((1u << K2_WARPS) - 1u, s, off);
        if (threadIdx.x == 0) atomicAdd(out, s);
    }
}

// ---------------------------------------------------------------------------
extern "C" void kernel_launch(void* const* d_in, const int* in_sizes, int n_in,
                              void* d_out, int out_size)
{
    const float* xyz = (const float*)d_in[0];
    const float* rot = (const float*)d_in[1];
    const float* scl = (const float*)d_in[2];
    const float* col = (const float*)d_in[3];
    const float* opa = (const float*)d_in[4];
    float* out = (float*)d_out;

    zero_kernel<<<(Bsz * NC3 + 255) / 256, 256>>>(out);
    count_kernel<<<NQ / 256, 256>>>(xyz);
    scan_kernel<<<Bsz, SCAN_T>>>();
    scatter_kernel<<<NQ / 256, 256>>>(xyz);
    knn_kernel<<<NQ / 128, 128>>>();
    loss_kernel<<<NQ / K2_WARPS, K2_THREADS>>>(rot, scl, col, opa, out);
}

// round 11
// speedup vs baseline: 6.8805x; 1.4149x over previous
#include <cuda_runtime.h>
#include <cuda_bf16.h>
#include <math.h>

// Problem constants
#define Bsz   2
#define Npts  8192
#define Kn    3
#define NQ    (Bsz * Npts)

// Spatial grid: [-6,6]^3, cell 0.5 -> 24^3 cells, ~65 pts/cell at center
#define GRD   24
#define NC3   (GRD * GRD * GRD)       // 13824 cells
#define CS    0.5f
#define INVCS 2.0f
#define ORG   (-6.0f)

#define FULLMASK 0xffffffffu

// Device scratch (static — no allocations)
__device__ int    g_cnt[Bsz * NC3];
__device__ int    g_off[Bsz * (NC3 + 1)];
__device__ int    g_cur[Bsz * NC3];
__device__ float4 g_pts[NQ];          // sorted {-2x,-2y,-2z,|s|^2}
__device__ int    g_sidx[NQ];         // sorted -> original local index
__device__ int    g_nn[NQ * 3];       // per ORIGINAL query: 3 neighbor orig indices
__device__ float  g_dsum[NQ];         // per ORIGINAL query: d0+d1+d2

__device__ __forceinline__ int clampi(int v, int lo, int hi) {
    return v < lo ? lo : (v > hi ? hi : v);
}
__device__ __forceinline__ void cell_coords(float x, float y, float z,
                                            int& ci, int& cj, int& ck) {
    ci = clampi((int)floorf((x - ORG) * INVCS), 0, GRD - 1);
    cj = clampi((int)floorf((y - ORG) * INVCS), 0, GRD - 1);
    ck = clampi((int)floorf((z - ORG) * INVCS), 0, GRD - 1);
}

// Replicated top-3 insert (all lanes execute identically), strict <.
__device__ __forceinline__ void insert3(float f, int cand,
                                        float& t0, float& t1, float& t2,
                                        int& i0, int& i1, int& i2)
{
    if (f < t2) {
        if (f < t0)      { t2 = t1; i2 = i1; t1 = t0; i1 = i0; t0 = f; i0 = cand; }
        else if (f < t1) { t2 = t1; i2 = i1; t1 = f;  i1 = cand; }
        else             { t2 = f;  i2 = cand; }
    }
}

// ---------------------------------------------------------------------------
__global__ void zero_kernel(float* out) {
    const int t = blockIdx.x * blockDim.x + threadIdx.x;
    if (t < Bsz * NC3) g_cnt[t] = 0;
    if (t == 0) out[0] = 0.0f;
}

__global__ void count_kernel(const float* __restrict__ xyz) {
    const int t = blockIdx.x * blockDim.x + threadIdx.x;
    if (t >= NQ) return;
    const int b = t >> 13, p = t & (Npts - 1);
    const float* xp = xyz + ((size_t)b * Npts + p) * 3;
    int ci, cj, ck;
    cell_coords(xp[0], xp[1], xp[2], ci, cj, ck);
    atomicAdd(&g_cnt[b * NC3 + (ci * GRD + cj) * GRD + ck], 1);
}

#define SCAN_T 512
__global__ __launch_bounds__(SCAN_T) void scan_kernel() {
    const int b   = blockIdx.x;
    const int tid = threadIdx.x;
    const int SPAN = NC3 / SCAN_T;    // 27
    const int base = b * NC3 + tid * SPAN;

    int s = 0;
    for (int i = 0; i < SPAN; i++) s += g_cnt[base + i];

    __shared__ int sm[SCAN_T];
    sm[tid] = s;
    __syncthreads();
    for (int d = 1; d < SCAN_T; d <<= 1) {
        int v = (tid >= d) ? sm[tid - d] : 0;
        __syncthreads();
        sm[tid] += v;
        __syncthreads();
    }
    int run = sm[tid] - s;

    const int obase = b * (NC3 + 1) + tid * SPAN;
    for (int i = 0; i < SPAN; i++) {
        const int c = g_cnt[base + i];
        g_off[obase + i] = run;
        g_cur[base + i]  = run;
        run += c;
    }
    if (tid == SCAN_T - 1) g_off[b * (NC3 + 1) + NC3] = run;
}

__global__ void scatter_kernel(const float* __restrict__ xyz) {
    const int t = blockIdx.x * blockDim.x + threadIdx.x;
    if (t >= NQ) return;
    const int b = t >> 13, p = t & (Npts - 1);
    const float* xp = xyz + ((size_t)b * Npts + p) * 3;
    const float x = xp[0], y = xp[1], z = xp[2];
    int ci, cj, ck;
    cell_coords(x, y, z, ci, cj, ck);
    const int pos = atomicAdd(&g_cur[b * NC3 + (ci * GRD + cj) * GRD + ck], 1);
    const float n = fmaf(x, x, fmaf(y, y, z * z));
    g_pts[(b << 13) + pos]  = make_float4(-2.0f * x, -2.0f * y, -2.0f * z, n);
    g_sidx[(b << 13) + pos] = p;
}

// ---------------------------------------------------------------------------
// Warp-parallel exact KNN. One WARP per sorted query.
//   Phase A: lanes scan the query's own cell (ballot-gated inserts after a
//            3-round lex-argmin prologue on the first <=32 candidates).
//   Phase B: lanes 0..25 compute exact box distances to the 26 neighbor
//            cells; scan only cells with boxdist^2 < current d3.
//   Safety:  shells r>=2 only while d3 > ((r-1)*CS)^2 (rare tail).
// Top-3 state is replicated across all lanes (identical ops) -> no divergence.
// ---------------------------------------------------------------------------
__global__ __launch_bounds__(128) void knn_kernel() {
    const int lane = threadIdx.x & 31;
    const int j    = blockIdx.x * 4 + (threadIdx.x >> 5);  // sorted slot
    const int b  = j >> 13;
    const int pb = b << 13;
    const int ob = b * (NC3 + 1);

    const float4 q4 = g_pts[j];
    const float qx = -0.5f * q4.x;
    const float qy = -0.5f * q4.y;
    const float qz = -0.5f * q4.z;
    const float qn = q4.w;

    int qi, qj, qk;
    cell_coords(qx, qy, qz, qi, qj, qk);

    float t0 = INFINITY, t1 = INFINITY, t2 = INFINITY;
    int   n0 = 0x7fffffff, n1 = 0x7fffffff, n2 = 0x7fffffff;

    // ---- Phase A: own cell ----
    {
        const int cc = ob + (qi * GRD + qj) * GRD + qk;
        const int s  = g_off[cc];
        const int e  = g_off[cc + 1];
        bool first = true;
        for (int p0 = s; p0 < e; p0 += 32) {
            const int p = p0 + lane;
            float t = INFINITY; int oi = 0x7fffffff;
            if (p < e) {
                const float4 c4 = g_pts[pb + p];
                float tt = fmaf(qx, c4.x, c4.w);
                tt = fmaf(qy, c4.y, tt);
                t  = fmaf(qz, c4.z, tt);
                oi = g_sidx[pb + p];
            }
            if (first) {
                first = false;
                float v = t; int iv = oi;
                #pragma unroll
                for (int r = 0; r < Kn; r++) {
                    float bv = v; int bi = iv;
                    #pragma unroll
                    for (int off = 16; off > 0; off >>= 1) {
                        const float ov = __shfl_xor_sync(FULLMASK, bv, off);
                        const int   oo = __shfl_xor_sync(FULLMASK, bi, off);
                        if (ov < bv || (ov == bv && oo < bi)) { bv = ov; bi = oo; }
                    }
                    if (r == 0)      { t0 = bv; n0 = bi; }
                    else if (r == 1) { t1 = bv; n1 = bi; }
                    else             { t2 = bv; n2 = bi; }
                    if (iv == bi) v = INFINITY;
                }
            } else {
                unsigned bal = __ballot_sync(FULLMASK, t < t2);
                while (bal) {
                    const int l = __ffs(bal) - 1;
                    bal &= bal - 1;
                    const float tv = __shfl_sync(FULLMASK, t,  l);
                    const int   ov = __shfl_sync(FULLMASK, oi, l);
                    insert3(tv, ov, t0, t1, t2, n0, n1, n2);
                }
            }
        }
    }

    // ---- Phase B: 26 neighbor cells, pruned by exact box distance ----
    {
        float bd2 = INFINITY;
        int   ncc = 0;
        if (lane < 26) {
            const int l27 = (lane < 13) ? lane : lane + 1;    // skip center (13)
            const int ci = qi + l27 / 9 - 1;
            const int cj = qj + (l27 / 3) % 3 - 1;
            const int ck = qk + l27 % 3 - 1;
            if (ci >= 0 && ci < GRD && cj >= 0 && cj < GRD && ck >= 0 && ck < GRD) {
                ncc = (ci * GRD + cj) * GRD + ck;
                const float lox = ORG + ci * CS, hix = lox + CS;
                const float loy = ORG + cj * CS, hiy = loy + CS;
                const float loz = ORG + ck * CS, hiz = loz + CS;
                const float dx = fmaxf(fmaxf(lox - qx, qx - hix), 0.0f);
                const float dy = fmaxf(fmaxf(loy - qy, qy - hiy), 0.0f);
                const float dz = fmaxf(fmaxf(loz - qz, qz - hiz), 0.0f);
                bd2 = fmaf(dx, dx, fmaf(dy, dy, dz * dz));
            }
        }
        unsigned mask = __ballot_sync(FULLMASK, bd2 < t2 + qn);
        while (mask) {
            const int l = __ffs(mask) - 1;
            mask &= mask - 1;
            const float bd2l = __shfl_sync(FULLMASK, bd2, l);
            if (bd2l >= t2 + qn) continue;                    // d3 shrank: skip
            const int cc = ob + __shfl_sync(FULLMASK, ncc, l);
            const int s  = g_off[cc];
            const int e  = g_off[cc + 1];
            for (int p0 = s; p0 < e; p0 += 32) {
                const int p = p0 + lane;
                float t = INFINITY; int oi = 0x7fffffff;
                if (p < e) {
                    const float4 c4 = g_pts[pb + p];
                    float tt = fmaf(qx, c4.x, c4.w);
                    tt = fmaf(qy, c4.y, tt);
                    t  = fmaf(qz, c4.z, tt);
                    oi = g_sidx[pb + p];
                }
                unsigned bal = __ballot_sync(FULLMASK, t < t2);
                while (bal) {
                    const int bl = __ffs(bal) - 1;
                    bal &= bal - 1;
                    const float tv = __shfl_sync(FULLMASK, t,  bl);
                    const int   ov = __shfl_sync(FULLMASK, oi, bl);
                    insert3(tv, ov, t0, t1, t2, n0, n1, n2);
                }
            }
        }
    }

    // ---- Safety shells r>=2 (rare: sparse tail cells) ----
    for (int r = 2; r < GRD; r++) {
        const float g = (float)(r - 1) * CS;
        if (t2 + qn <= g * g * 0.9999f) break;
        const int ilo = qi - r < 0 ? 0 : qi - r;
        const int ihi = qi + r > GRD - 1 ? GRD - 1 : qi + r;
        const int jlo = qj - r < 0 ? 0 : qj - r;
        const int jhi = qj + r > GRD - 1 ? GRD - 1 : qj + r;
        const int klo = qk - r < 0 ? 0 : qk - r;
        const int khi = qk + r > GRD - 1 ? GRD - 1 : qk + r;
        for (int ci = ilo; ci <= ihi; ci++) {
            const int adi = abs(ci - qi);
            for (int cj = jlo; cj <= jhi; cj++) {
                const bool faceij = (adi == r) || (abs(cj - qj) == r);
                const int rowb = ob + (ci * GRD + cj) * GRD;
                for (int ck = klo; ck <= khi; ck++) {
                    if (!faceij && abs(ck - qk) != r) continue;
                    const int cc = rowb + ck;
                    const int s  = g_off[cc];
                    const int e  = g_off[cc + 1];
                    for (int p0 = s; p0 < e; p0 += 32) {
                        const int p = p0 + lane;
                        float t = INFINITY; int oi = 0x7fffffff;
                        if (p < e) {
                            const float4 c4 = g_pts[pb + p];
                            float tt = fmaf(qx, c4.x, c4.w);
                            tt = fmaf(qy, c4.y, tt);
                            t  = fmaf(qz, c4.z, tt);
                            oi = g_sidx[pb + p];
                        }
                        unsigned bal = __ballot_sync(FULLMASK, t < t2);
                        while (bal) {
                            const int bl = __ffs(bal) - 1;
                            bal &= bal - 1;
                            const float tv = __shfl_sync(FULLMASK, t,  bl);
                            const int   ov = __shfl_sync(FULLMASK, oi, bl);
                            insert3(tv, ov, t0, t1, t2, n0, n1, n2);
                        }
                    }
                }
            }
        }
    }

    if (lane == 0) {
        const int orig = g_sidx[j];
        const int gq   = pb + orig;
        g_nn[gq * 3 + 0] = n0;
        g_nn[gq * 3 + 1] = n1;
        g_nn[gq * 3 + 2] = n2;
        g_dsum[gq] = (t0 + qn) + (t1 + qn) + (t2 + qn);
    }
}

// ---------------------------------------------------------------------------
// Loss: warp per query (proven structure), reads g_nn / g_dsum.
// ---------------------------------------------------------------------------
#define K2_THREADS 256
#define K2_WARPS   (K2_THREADS / 32)

__global__ __launch_bounds__(K2_THREADS) void loss_kernel(
    const float* __restrict__ rot,  // [B,N,4]
    const float* __restrict__ scl,  // [B,N,3]
    const float* __restrict__ col,  // [B,N,45]
    const float* __restrict__ opa,  // [B,N,1]
    float* __restrict__ out)
{
    const int lane = threadIdx.x & 31;
    const int wid  = threadIdx.x >> 5;
    const int gq   = blockIdx.x * K2_WARPS + wid;
    const int b    = gq >> 13;

    const int r0 = b * Npts + g_nn[gq * 3 + 0];
    const int r1 = b * Npts + g_nn[gq * 3 + 1];
    const int r2 = b * Npts + g_nn[gq * 3 + 2];

    float local = 0.0f;
    if (lane == 0)
        local += g_dsum[gq] * (1.0f / ((float)Bsz * Npts * Kn));

    // 53 channels: 0..3 rot(C=4), 4..6 scales(C=3), 7 opacity(C=1), 8..52 colors(C=45)
    for (int c = lane; c < 53; c += 32) {
        const float* bp; int C; int cc;
        if (c < 4)       { bp = rot; C = 4;  cc = c;     }
        else if (c < 7)  { bp = scl; C = 3;  cc = c - 4; }
        else if (c < 8)  { bp = opa; C = 1;  cc = 0;     }
        else             { bp = col; C = 45; cc = c - 8; }

        const float x0 = __ldg(bp + (size_t)r0 * C + cc);
        const float x1 = __ldg(bp + (size_t)r1 * C + cc);
        const float x2 = __ldg(bp + (size_t)r2 * C + cc);

        const float m  = (x0 + x1 + x2) * (1.0f / 3.0f);
        const float e0 = x0 - m, e1 = x1 - m, e2 = x2 - m;
        const float var = fmaf(e0, e0, fmaf(e1, e1, e2 * e2)) * 0.5f;  // ddof=1
        local += sqrtf(var) * (1.0f / ((float)Bsz * Npts * (float)C));
    }

    #pragma unroll
    for (int off = 16; off > 0; off >>= 1)
        local += __shfl_xor_sync(0xffffffffu, local, off);

    __shared__ float red[K2_WARPS];
    if (lane == 0) red[wid] = local;
    __syncthreads();

    if (threadIdx.x < K2_WARPS) {
        float s = red[threadIdx.x];
        #pragma unroll
        for (int off = K2_WARPS / 2; off > 0; off >>= 1)
            s += __shfl_xor_sync((1u << K2_WARPS) - 1u, s, off);
        if (threadIdx.x == 0) atomicAdd(out, s);
    }
}

// ---------------------------------------------------------------------------
extern "C" void kernel_launch(void* const* d_in, const int* in_sizes, int n_in,
                              void* d_out, int out_size)
{
    const float* xyz = (const float*)d_in[0];
    const float* rot = (const float*)d_in[1];
    const float* scl = (const float*)d_in[2];
    const float* col = (const float*)d_in[3];
    const float* opa = (const float*)d_in[4];
    float* out = (float*)d_out;

    zero_kernel<<<(Bsz * NC3 + 255) / 256, 256>>>(out);
    count_kernel<<<NQ / 256, 256>>>(xyz);
    scan_kernel<<<Bsz, SCAN_T>>>();
    scatter_kernel<<<NQ / 256, 256>>>(xyz);
    knn_kernel<<<NQ / 4, 128>>>();
    loss_kernel<<<NQ / K2_WARPS, K2_THREADS>>>(rot, scl, col, opa, out);
}

// round 12
// speedup vs baseline: 9.9276x; 1.4429x over previous
#include <cuda_runtime.h>
#include <cuda_bf16.h>
#include <math.h>

// Problem constants
#define Bsz     2
#define Npts    8192
#define Kn      3
#define NQ      (Bsz * Npts)
#define THREADS 128
#define WARPS   (THREADS / 32)
#define G       4                  // queries per warp
#define QPB     (WARPS * G)        // 16 queries per block
#define TILE_C  1024               // candidates per smem tile
#define NTILES  (Npts / TILE_C)    // 8 tiles
#define PAD     32                 // +inf pad rows (guard-free prefetch)

#define FULLMASK 0xffffffffu
typedef unsigned long long u64;

#define PACK_F32X2(out, lo, hi) \
    asm("mov.b64 %0, {%1, %2};" : "=l"(out) : "f"(lo), "f"(hi))
#define UNPACK_F32X2(lo, hi, in) \
    asm("mov.b64 {%0, %1}, %2;" : "=f"(lo), "=f"(hi) : "l"(in))
#define FMA_F32X2(out, a, b, c) \
    asm("fma.rn.f32x2 %0, %1, %2, %3;" : "=l"(out) : "l"(a), "l"(b), "l"(c))

// Top-3 insert, strict < in ascending candidate order (= top_k tie-break)
__device__ __forceinline__ void insert3(float f, int cand,
                                        float& t0, float& t1, float& t2,
                                        int& i0, int& i1, int& i2)
{
    if (f < t2) {
        if (f < t0)      { t2 = t1; i2 = i1; t1 = t0; i1 = i0; t0 = f; i0 = cand; }
        else if (f < t1) { t2 = t1; i2 = i1; t1 = f;  i1 = cand; }
        else             { t2 = f;  i2 = cand; }
    }
}

__global__ void zero_out_kernel(float* out) { out[0] = 0.0f; }

// ---------------------------------------------------------------------------
// Fused KNN + loss (R8 structure). Warp owns G=4 queries; lanes scan 32
// distinct candidates per step. Candidates staged duplicated:
//   scA = {-2x,-2x,-2y,-2y}, scB = {-2z,-2z,|s|^2,|s|^2}
// so the distance chain is 6 packed f32x2 FFMAs per step (4 queries x 32
// candidates = 128 pairs). t = qx*(-2x) + qy*(-2y) + (qz*(-2z) + n), monotone
// in d for fixed query. Prefetch next step's pair before gating (LDS latency
// hidden); tile has PAD rows with n=+inf so no guard needed.
// ---------------------------------------------------------------------------
__global__ __launch_bounds__(THREADS) void knnreg_kernel(
    const float* __restrict__ xyz,   // [B,N,3]
    const float* __restrict__ rot,   // [B,N,4]
    const float* __restrict__ scl,   // [B,N,3]
    const float* __restrict__ col,   // [B,N,45]
    const float* __restrict__ opa,   // [B,N,1]
    float* __restrict__ out)
{
    const int tid  = threadIdx.x;
    const int lane = tid & 31;
    const int wid  = tid >> 5;
    const int qblk = blockIdx.x * QPB;
    const int b    = qblk >> 13;
    const float* xb = xyz + (size_t)b * Npts * 3;
    const int qw   = (qblk & (Npts - 1)) + wid * G;

    // Load the warp's 4 queries (broadcast) and pack
    float qx[G], qy[G], qz[G], qn[G];
    #pragma unroll
    for (int g = 0; g < G; g++) {
        const int q = qw + g;
        qx[g] = xb[q * 3 + 0];
        qy[g] = xb[q * 3 + 1];
        qz[g] = xb[q * 3 + 2];
        qn[g] = fmaf(qx[g], qx[g], fmaf(qy[g], qy[g], qz[g] * qz[g]));
    }
    u64 qx01, qx23, qy01, qy23, qz01, qz23;
    PACK_F32X2(qx01, qx[0], qx[1]); PACK_F32X2(qx23, qx[2], qx[3]);
    PACK_F32X2(qy01, qy[0], qy[1]); PACK_F32X2(qy23, qy[2], qy[3]);
    PACK_F32X2(qz01, qz[0], qz[1]); PACK_F32X2(qz23, qz[2], qz[3]);

    float t0[G], t1[G], t2[G];
    int   i0[G], i1[G], i2[G];

    __shared__ float4 scA[TILE_C + PAD];  // {-2x,-2x,-2y,-2y}
    __shared__ float4 scB[TILE_C + PAD];  // {-2z,-2z, n, n}
    __shared__ float  red[WARPS];

    // Pad rows: n=+inf => t=+inf, can never insert. Written once.
    for (int k = tid; k < PAD; k += THREADS) {
        scA[TILE_C + k] = make_float4(0.f, 0.f, 0.f, 0.f);
        scB[TILE_C + k] = make_float4(0.f, 0.f, INFINITY, INFINITY);
    }

    // ---- stage tile 0 ----
    for (int k = tid; k < TILE_C; k += THREADS) {
        const float x = xb[k * 3 + 0];
        const float y = xb[k * 3 + 1];
        const float z = xb[k * 3 + 2];
        const float n = fmaf(x, x, fmaf(y, y, z * z));
        scA[k] = make_float4(-2.0f * x, -2.0f * x, -2.0f * y, -2.0f * y);
        scB[k] = make_float4(-2.0f * z, -2.0f * z, n, n);
    }
    __syncthreads();

    // ---- prologue: candidates 0..31 via warp lex-argmin (exact) ----
    {
        const float4 a = scA[lane];
        const float4 bB = scB[lane];
        #pragma unroll
        for (int g = 0; g < G; g++) {
            // same chain order as main loop: qz innermost with n
            float t = fmaf(qz[g], bB.x, bB.z);
            t = fmaf(qy[g], a.z, t);
            t = fmaf(qx[g], a.x, t);
            float v = t; int iv = lane;
            float rt[Kn]; int ri[Kn];
            #pragma unroll
            for (int r = 0; r < Kn; r++) {
                float bv = v; int bi = iv;
                #pragma unroll
                for (int off = 16; off > 0; off >>= 1) {
                    const float ov = __shfl_xor_sync(FULLMASK, bv, off);
                    const int   oo = __shfl_xor_sync(FULLMASK, bi, off);
                    if (ov < bv || (ov == bv && oo < bi)) { bv = ov; bi = oo; }
                }
                rt[r] = bv; ri[r] = bi;
                if (iv == bi) v = INFINITY;
            }
            t0[g] = rt[0]; t1[g] = rt[1]; t2[g] = rt[2];
            i0[g] = ri[0]; i1[g] = ri[1]; i2[g] = ri[2];
        }
    }

    // ---- main scan (packed, prefetched) ----
    for (int tile = 0; tile < NTILES; tile++) {
        if (tile > 0) {
            __syncthreads();
            const int base = tile * TILE_C;
            for (int k = tid; k < TILE_C; k += THREADS) {
                const int j = base + k;
                const float x = xb[j * 3 + 0];
                const float y = xb[j * 3 + 1];
                const float z = xb[j * 3 + 2];
                const float n = fmaf(x, x, fmaf(y, y, z * z));
                scA[k] = make_float4(-2.0f * x, -2.0f * x, -2.0f * y, -2.0f * y);
                scB[k] = make_float4(-2.0f * z, -2.0f * z, n, n);
            }
            __syncthreads();
        }

        const int sbeg  = (tile == 0) ? 32 : 0;
        const int tbase = tile * TILE_C;

        float4 a  = scA[sbeg + lane];
        float4 bb = scB[sbeg + lane];

        for (int s = sbeg; s < TILE_C; s += 32) {
            // prefetch next (pad rows make this always safe)
            const float4 an = scA[s + 32 + lane];
            const float4 bn = scB[s + 32 + lane];

            // packed distance chain
            const u64 axx = *reinterpret_cast<const u64*>(&a.x);   // {-2x,-2x}
            const u64 ayy = *reinterpret_cast<const u64*>(&a.z);   // {-2y,-2y}
            const u64 bzz = *reinterpret_cast<const u64*>(&bb.x);  // {-2z,-2z}
            const u64 bnn = *reinterpret_cast<const u64*>(&bb.z);  // {n,n}

            u64 t01, t23;
            FMA_F32X2(t01, qz01, bzz, bnn);
            FMA_F32X2(t01, qy01, ayy, t01);
            FMA_F32X2(t01, qx01, axx, t01);
            FMA_F32X2(t23, qz23, bzz, bnn);
            FMA_F32X2(t23, qy23, ayy, t23);
            FMA_F32X2(t23, qx23, axx, t23);

            float tg[G];
            UNPACK_F32X2(tg[0], tg[1], t01);
            UNPACK_F32X2(tg[2], tg[3], t23);

            const bool p = (tg[0] < t2[0]) | (tg[1] < t2[1])
                         | (tg[2] < t2[2]) | (tg[3] < t2[3]);
            if (__ballot_sync(FULLMASK, p)) {
                const int cb = tbase + s;
                #pragma unroll
                for (int g = 0; g < G; g++) {
                    unsigned bg = __ballot_sync(FULLMASK, tg[g] < t2[g]);
                    while (bg) {
                        const int l = __ffs(bg) - 1;
                        bg &= bg - 1;
                        const float tv = __shfl_sync(FULLMASK, tg[g], l);
                        insert3(tv, cb + l,
                                t0[g], t1[g], t2[g], i0[g], i1[g], i2[g]);
                    }
                }
            }
            a = an; bb = bn;
        }
    }

    // ---- fused loss phase ----
    float local = 0.0f;

    #pragma unroll
    for (int g = 0; g < G; g++) {
        if (lane == 0) {
            local += ((t0[g] + qn[g]) + (t1[g] + qn[g]) + (t2[g] + qn[g]))
                     * (1.0f / ((float)Bsz * Npts * Kn));
        }

        const int r0 = b * Npts + i0[g];
        const int r1 = b * Npts + i1[g];
        const int r2 = b * Npts + i2[g];

        // 53 channels: 0..3 rot(4), 4..6 scales(3), 7 opacity(1), 8..52 colors(45)
        for (int c = lane; c < 53; c += 32) {
            const float* bp; int C; int cc;
            if (c < 4)       { bp = rot; C = 4;  cc = c;     }
            else if (c < 7)  { bp = scl; C = 3;  cc = c - 4; }
            else if (c < 8)  { bp = opa; C = 1;  cc = 0;     }
            else             { bp = col; C = 45; cc = c - 8; }

            const float x0 = __ldg(bp + (size_t)r0 * C + cc);
            const float x1 = __ldg(bp + (size_t)r1 * C + cc);
            const float x2 = __ldg(bp + (size_t)r2 * C + cc);

            const float m  = (x0 + x1 + x2) * (1.0f / 3.0f);
            const float e0 = x0 - m, e1 = x1 - m, e2 = x2 - m;
            const float var = fmaf(e0, e0, fmaf(e1, e1, e2 * e2)) * 0.5f; // ddof=1
            local += sqrtf(var) * (1.0f / ((float)Bsz * Npts * (float)C));
        }
    }

    #pragma unroll
    for (int off = 16; off > 0; off >>= 1)
        local += __shfl_xor_sync(FULLMASK, local, off);

    __syncthreads();
    if (lane == 0) red[wid] = local;
    __syncthreads();

    if (tid == 0) {
        float s = 0.0f;
        #pragma unroll
        for (int w = 0; w < WARPS; w++) s += red[w];
        atomicAdd(out, s);
    }
}

// ---------------------------------------------------------------------------
extern "C" void kernel_launch(void* const* d_in, const int* in_sizes, int n_in,
                              void* d_out, int out_size)
{
    const float* xyz = (const float*)d_in[0];
    const float* rot = (const float*)d_in[1];
    const float* scl = (const float*)d_in[2];
    const float* col = (const float*)d_in[3];
    const float* opa = (const float*)d_in[4];
    float* out = (float*)d_out;

    zero_out_kernel<<<1, 1>>>(out);
    knnreg_kernel<<<NQ / QPB, THREADS>>>(xyz, rot, scl, col, opa, out);
}

// round 13
// speedup vs baseline: 10.9239x; 1.1004x over previous
#include <cuda_runtime.h>
#include <cuda_bf16.h>
#include <math.h>

// Problem constants
#define Bsz     2
#define Npts    8192
#define Kn      3
#define NQ      (Bsz * Npts)
#define THREADS 128
#define WARPS   (THREADS / 32)     // 4 warps per block
#define G       2                  // queries per warp (occupancy knob)
#define QPB     (WARPS * G)        // 8 queries per block -> 2048 blocks
#define TILE_C  1024               // candidates per smem tile
#define NTILES  (Npts / TILE_C)    // 8 tiles

#define FULLMASK 0xffffffffu

// Precomputed candidate vectors {-2x, -2y, -2z, |s|^2}
__device__ float4 g_c4[NQ];

// Top-3 insert, strict < in ascending candidate order (= top_k tie-break)
__device__ __forceinline__ void insert3(float f, int cand,
                                        float& t0, float& t1, float& t2,
                                        int& i0, int& i1, int& i2)
{
    if (f < t2) {
        if (f < t0)      { t2 = t1; i2 = i1; t1 = t0; i1 = i0; t0 = f; i0 = cand; }
        else if (f < t1) { t2 = t1; i2 = i1; t1 = f;  i1 = cand; }
        else             { t2 = f;  i2 = cand; }
    }
}

// Prep: build g_c4 and zero the output accumulator.
__global__ void prep_kernel(const float* __restrict__ xyz, float* __restrict__ out)
{
    const int t = blockIdx.x * blockDim.x + threadIdx.x;
    if (t == 0) out[0] = 0.0f;
    if (t >= NQ) return;
    const float x = xyz[t * 3 + 0];
    const float y = xyz[t * 3 + 1];
    const float z = xyz[t * 3 + 2];
    const float n = fmaf(x, x, fmaf(y, y, z * z));
    g_c4[t] = make_float4(-2.0f * x, -2.0f * y, -2.0f * z, n);
}

// ---------------------------------------------------------------------------
// Fused KNN + loss (proven R8 structure). Warp owns G=2 queries; lanes scan
// 32 distinct candidates per step in t-space (t = (-2s).q + |s|^2, monotone
// in d per query). Ballot-gated exact inserts; ascending-bit iteration keeps
// jax.lax.top_k tie-break semantics. Prologue: first 32 candidates via 3
// rounds of warp lexicographic argmin (t, idx).
// ---------------------------------------------------------------------------
__global__ __launch_bounds__(THREADS) void knnreg_kernel(
    const float* __restrict__ xyz,   // [B,N,3]
    const float* __restrict__ rot,   // [B,N,4]
    const float* __restrict__ scl,   // [B,N,3]
    const float* __restrict__ col,   // [B,N,45]
    const float* __restrict__ opa,   // [B,N,1]
    float* __restrict__ out)
{
    const int tid  = threadIdx.x;
    const int lane = tid & 31;
    const int wid  = tid >> 5;
    const int qblk = blockIdx.x * QPB;
    const int b    = qblk >> 13;                 // QPB=8 | 8192
    const float* xb = xyz + (size_t)b * Npts * 3;
    const float4* cb4 = g_c4 + (size_t)b * Npts;
    const int qw   = (qblk & (Npts - 1)) + wid * G;

    // Warp's queries (broadcast loads)
    float qx[G], qy[G], qz[G], qn[G];
    #pragma unroll
    for (int g = 0; g < G; g++) {
        const int q = qw + g;
        qx[g] = xb[q * 3 + 0];
        qy[g] = xb[q * 3 + 1];
        qz[g] = xb[q * 3 + 2];
        qn[g] = fmaf(qx[g], qx[g], fmaf(qy[g], qy[g], qz[g] * qz[g]));
    }

    float t0[G], t1[G], t2[G];
    int   i0[G], i1[G], i2[G];

    __shared__ float4 sc[TILE_C];
    __shared__ float  red[WARPS];

    // ---- stage tile 0 (LDG.128 -> STS.128) ----
    for (int k = tid; k < TILE_C; k += THREADS)
        sc[k] = cb4[k];
    __syncthreads();

    // ---- prologue: candidates 0..31 via warp lex-argmin (exact) ----
    {
        const float4 c = sc[lane];
        #pragma unroll
        for (int g = 0; g < G; g++) {
            float t = fmaf(qx[g], c.x, c.w);
            t = fmaf(qy[g], c.y, t);
            t = fmaf(qz[g], c.z, t);
            float v = t; int iv = lane;
            float rt[Kn]; int ri[Kn];
            #pragma unroll
            for (int r = 0; r < Kn; r++) {
                float bv = v; int bi = iv;
                #pragma unroll
                for (int off = 16; off > 0; off >>= 1) {
                    const float ov = __shfl_xor_sync(FULLMASK, bv, off);
                    const int   oo = __shfl_xor_sync(FULLMASK, bi, off);
                    if (ov < bv || (ov == bv && oo < bi)) { bv = ov; bi = oo; }
                }
                rt[r] = bv; ri[r] = bi;
                if (iv == bi) v = INFINITY;
            }
            t0[g] = rt[0]; t1[g] = rt[1]; t2[g] = rt[2];
            i0[g] = ri[0]; i1[g] = ri[1]; i2[g] = ri[2];
        }
    }

    // ---- main scan ----
    for (int tile = 0; tile < NTILES; tile++) {
        if (tile > 0) {
            __syncthreads();
            const int base = tile * TILE_C;
            for (int k = tid; k < TILE_C; k += THREADS)
                sc[k] = cb4[base + k];
            __syncthreads();
        }

        const int sbeg  = (tile == 0) ? 32 : 0;
        const int tbase = tile * TILE_C;
        for (int s = sbeg; s < TILE_C; s += 32) {
            const float4 c = sc[s + lane];
            float tg[G];
            #pragma unroll
            for (int g = 0; g < G; g++) {
                float t = fmaf(qx[g], c.x, c.w);
                t = fmaf(qy[g], c.y, t);
                tg[g] = fmaf(qz[g], c.z, t);
            }
            const bool p = (tg[0] < t2[0]) | (tg[1] < t2[1]);
            if (__ballot_sync(FULLMASK, p)) {
                const int cbd = tbase + s;
                #pragma unroll
                for (int g = 0; g < G; g++) {
                    unsigned bg = __ballot_sync(FULLMASK, tg[g] < t2[g]);
                    while (bg) {
                        const int l = __ffs(bg) - 1;
                        bg &= bg - 1;
                        const float tv = __shfl_sync(FULLMASK, tg[g], l);
                        insert3(tv, cbd + l,
                                t0[g], t1[g], t2[g], i0[g], i1[g], i2[g]);
                    }
                }
            }
        }
    }

    // ---- fused loss phase ----
    float local = 0.0f;

    #pragma unroll
    for (int g = 0; g < G; g++) {
        if (lane == 0) {
            local += ((t0[g] + qn[g]) + (t1[g] + qn[g]) + (t2[g] + qn[g]))
                     * (1.0f / ((float)Bsz * Npts * Kn));
        }

        const int r0 = b * Npts + i0[g];
        const int r1 = b * Npts + i1[g];
        const int r2 = b * Npts + i2[g];

        // 53 channels: 0..3 rot(4), 4..6 scales(3), 7 opacity(1), 8..52 colors(45)
        for (int c = lane; c < 53; c += 32) {
            const float* bp; int C; int cc;
            if (c < 4)       { bp = rot; C = 4;  cc = c;     }
            else if (c < 7)  { bp = scl; C = 3;  cc = c - 4; }
            else if (c < 8)  { bp = opa; C = 1;  cc = 0;     }
            else             { bp = col; C = 45; cc = c - 8; }

            const float x0 = __ldg(bp + (size_t)r0 * C + cc);
            const float x1 = __ldg(bp + (size_t)r1 * C + cc);
            const float x2 = __ldg(bp + (size_t)r2 * C + cc);

            const float m  = (x0 + x1 + x2) * (1.0f / 3.0f);
            const float e0 = x0 - m, e1 = x1 - m, e2 = x2 - m;
            const float var = fmaf(e0, e0, fmaf(e1, e1, e2 * e2)) * 0.5f; // ddof=1
            local += sqrtf(var) * (1.0f / ((float)Bsz * Npts * (float)C));
        }
    }

    // warp reduce
    #pragma unroll
    for (int off = 16; off > 0; off >>= 1)
        local += __shfl_xor_sync(FULLMASK, local, off);

    __syncthreads();
    if (lane == 0) red[wid] = local;
    __syncthreads();

    if (tid == 0) {
        float s = 0.0f;
        #pragma unroll
        for (int w = 0; w < WARPS; w++) s += red[w];
        atomicAdd(out, s);
    }
}

// ---------------------------------------------------------------------------
extern "C" void kernel_launch(void* const* d_in, const int* in_sizes, int n_in,
                              void* d_out, int out_size)
{
    const float* xyz = (const float*)d_in[0];
    const float* rot = (const float*)d_in[1];
    const float* scl = (const float*)d_in[2];
    const float* col = (const float*)d_in[3];
    const float* opa = (const float*)d_in[4];
    float* out = (float*)d_out;

    prep_kernel<<<NQ / 256, 256>>>(xyz, out);
    knnreg_kernel<<<NQ / QPB, THREADS>>>(xyz, rot, scl, col, opa, out);
}

// round 14
// speedup vs baseline: 14.4504x; 1.3228x over previous
#include <cuda_runtime.h>
#include <cuda_bf16.h>
#include <math.h>

// Problem constants
#define Bsz     2
#define Npts    8192
#define Kn      3
#define NQ      (Bsz * Npts)
#define THREADS 128
#define WARPS   (THREADS / 32)     // 4 warps per block
#define G       4                  // queries per warp
#define QPB     (WARPS * G)        // 16 queries per block -> 1024 blocks
#define TILE_C  1024               // candidates per smem tile
#define NTILES  (Npts / TILE_C)    // 8 tiles

#define FULLMASK 0xffffffffu

// Precomputed candidate vectors {-2x, -2y, -2z, |s|^2}
__device__ float4 g_c4[NQ];

// Top-3 insert, strict < in ascending candidate order (= top_k tie-break).
// Rechecks f < t2, so stale ballot bits self-filter.
__device__ __forceinline__ void insert3(float f, int cand,
                                        float& t0, float& t1, float& t2,
                                        int& i0, int& i1, int& i2)
{
    if (f < t2) {
        if (f < t0)      { t2 = t1; i2 = i1; t1 = t0; i1 = i0; t0 = f; i0 = cand; }
        else if (f < t1) { t2 = t1; i2 = i1; t1 = f;  i1 = cand; }
        else             { t2 = f;  i2 = cand; }
    }
}

// Prep: build g_c4 and zero the output accumulator.
__global__ void prep_kernel(const float* __restrict__ xyz, float* __restrict__ out)
{
    const int t = blockIdx.x * blockDim.x + threadIdx.x;
    if (t == 0) out[0] = 0.0f;
    if (t >= NQ) return;
    const float x = xyz[t * 3 + 0];
    const float y = xyz[t * 3 + 1];
    const float z = xyz[t * 3 + 2];
    const float n = fmaf(x, x, fmaf(y, y, z * z));
    g_c4[t] = make_float4(-2.0f * x, -2.0f * y, -2.0f * z, n);
}

// Ballot-gated insert of a 32-candidate window for one query.
__device__ __forceinline__ void process_window(float tg, int cbase,
                                               float& t0, float& t1, float& t2,
                                               int& i0, int& i1, int& i2)
{
    unsigned bg = __ballot_sync(FULLMASK, tg < t2);
    while (bg) {
        const int l = __ffs(bg) - 1;
        bg &= bg - 1;
        const float tv = __shfl_sync(FULLMASK, tg, l);
        insert3(tv, cbase + l, t0, t1, t2, i0, i1, i2);
    }
}

// ---------------------------------------------------------------------------
// Fused KNN + loss (R8 structure, double-width steps). Warp owns G=4 queries;
// lanes process 64 distinct candidates per step (2 float4 loads per lane).
// t-space: t = (-2s).q + |s|^2 = d - |q|^2, monotone per query.
// Fast path per step: 2 LDS.128 + 24 FFMA + 8 FSETP-OR + 1 ballot.
// Slow path: per-query ballots over lo then hi window (ascending candidate
// order; insert3 rechecks) -> exact sequential strict-< semantics.
// ---------------------------------------------------------------------------
__global__ __launch_bounds__(THREADS) void knnreg_kernel(
    const float* __restrict__ xyz,   // [B,N,3]
    const float* __restrict__ rot,   // [B,N,4]
    const float* __restrict__ scl,   // [B,N,3]
    const float* __restrict__ col,   // [B,N,45]
    const float* __restrict__ opa,   // [B,N,1]
    float* __restrict__ out)
{
    const int tid  = threadIdx.x;
    const int lane = tid & 31;
    const int wid  = tid >> 5;
    const int qblk = blockIdx.x * QPB;
    const int b    = qblk >> 13;                 // QPB=16 | 8192
    const float* xb = xyz + (size_t)b * Npts * 3;
    const float4* cb4 = g_c4 + (size_t)b * Npts;
    const int qw   = (qblk & (Npts - 1)) + wid * G;

    // Warp's queries (broadcast loads)
    float qx[G], qy[G], qz[G], qn[G];
    #pragma unroll
    for (int g = 0; g < G; g++) {
        const int q = qw + g;
        qx[g] = xb[q * 3 + 0];
        qy[g] = xb[q * 3 + 1];
        qz[g] = xb[q * 3 + 2];
        qn[g] = fmaf(qx[g], qx[g], fmaf(qy[g], qy[g], qz[g] * qz[g]));
    }

    float t0[G], t1[G], t2[G];
    int   i0[G], i1[G], i2[G];

    __shared__ float4 sc[TILE_C];
    __shared__ float  red[WARPS];

    // ---- stage tile 0 (LDG.128 -> STS.128) ----
    for (int k = tid; k < TILE_C; k += THREADS)
        sc[k] = cb4[k];
    __syncthreads();

    // ---- prologue: candidates 0..31 via warp lex-argmin (exact) ----
    {
        const float4 c = sc[lane];
        #pragma unroll
        for (int g = 0; g < G; g++) {
            float t = fmaf(qx[g], c.x, c.w);
            t = fmaf(qy[g], c.y, t);
            t = fmaf(qz[g], c.z, t);
            float v = t; int iv = lane;
            float rt[Kn]; int ri[Kn];
            #pragma unroll
            for (int r = 0; r < Kn; r++) {
                float bv = v; int bi = iv;
                #pragma unroll
                for (int off = 16; off > 0; off >>= 1) {
                    const float ov = __shfl_xor_sync(FULLMASK, bv, off);
                    const int   oo = __shfl_xor_sync(FULLMASK, bi, off);
                    if (ov < bv || (ov == bv && oo < bi)) { bv = ov; bi = oo; }
                }
                rt[r] = bv; ri[r] = bi;
                if (iv == bi) v = INFINITY;
            }
            t0[g] = rt[0]; t1[g] = rt[1]; t2[g] = rt[2];
            i0[g] = ri[0]; i1[g] = ri[1]; i2[g] = ri[2];
        }
    }

    // ---- candidates 32..63 (single-width step, aligns main loop to 64) ----
    {
        const float4 c = sc[32 + lane];
        float tg[G];
        #pragma unroll
        for (int g = 0; g < G; g++) {
            float t = fmaf(qx[g], c.x, c.w);
            t = fmaf(qy[g], c.y, t);
            tg[g] = fmaf(qz[g], c.z, t);
        }
        const bool p = (tg[0] < t2[0]) | (tg[1] < t2[1])
                     | (tg[2] < t2[2]) | (tg[3] < t2[3]);
        if (__ballot_sync(FULLMASK, p)) {
            #pragma unroll
            for (int g = 0; g < G; g++)
                process_window(tg[g], 32, t0[g], t1[g], t2[g], i0[g], i1[g], i2[g]);
        }
    }

    // ---- main scan: 64 candidates per step ----
    for (int tile = 0; tile < NTILES; tile++) {
        if (tile > 0) {
            __syncthreads();
            const int base = tile * TILE_C;
            for (int k = tid; k < TILE_C; k += THREADS)
                sc[k] = cb4[base + k];
            __syncthreads();
        }

        const int sbeg  = (tile == 0) ? 64 : 0;
        const int tbase = tile * TILE_C;
        for (int s = sbeg; s < TILE_C; s += 64) {
            const float4 ca = sc[s + lane];
            const float4 cb = sc[s + 32 + lane];
            float ta[G], tb[G];
            #pragma unroll
            for (int g = 0; g < G; g++) {
                float t = fmaf(qx[g], ca.x, ca.w);
                t = fmaf(qy[g], ca.y, t);
                ta[g] = fmaf(qz[g], ca.z, t);
                float u = fmaf(qx[g], cb.x, cb.w);
                u = fmaf(qy[g], cb.y, u);
                tb[g] = fmaf(qz[g], cb.z, u);
            }
            const bool p = (ta[0] < t2[0]) | (ta[1] < t2[1])
                         | (ta[2] < t2[2]) | (ta[3] < t2[3])
                         | (tb[0] < t2[0]) | (tb[1] < t2[1])
                         | (tb[2] < t2[2]) | (tb[3] < t2[3]);
            if (__ballot_sync(FULLMASK, p)) {
                const int cbd = tbase + s;
                #pragma unroll
                for (int g = 0; g < G; g++) {
                    // lo window first, then hi: ascending candidate order
                    process_window(ta[g], cbd,      t0[g], t1[g], t2[g], i0[g], i1[g], i2[g]);
                    process_window(tb[g], cbd + 32, t0[g], t1[g], t2[g], i0[g], i1[g], i2[g]);
                }
            }
        }
    }

    // ---- fused loss phase ----
    float local = 0.0f;

    #pragma unroll
    for (int g = 0; g < G; g++) {
        if (lane == 0) {
            local += ((t0[g] + qn[g]) + (t1[g] + qn[g]) + (t2[g] + qn[g]))
                     * (1.0f / ((float)Bsz * Npts * Kn));
        }

        const int r0 = b * Npts + i0[g];
        const int r1 = b * Npts + i1[g];
        const int r2 = b * Npts + i2[g];

        // 53 channels: 0..3 rot(4), 4..6 scales(3), 7 opacity(1), 8..52 colors(45)
        for (int c = lane; c < 53; c += 32) {
            const float* bp; int C; int cc;
            if (c < 4)       { bp = rot; C = 4;  cc = c;     }
            else if (c < 7)  { bp = scl; C = 3;  cc = c - 4; }
            else if (c < 8)  { bp = opa; C = 1;  cc = 0;     }
            else             { bp = col; C = 45; cc = c - 8; }

            const float x0 = __ldg(bp + (size_t)r0 * C + cc);
            const float x1 = __ldg(bp + (size_t)r1 * C + cc);
            const float x2 = __ldg(bp + (size_t)r2 * C + cc);

            const float m  = (x0 + x1 + x2) * (1.0f / 3.0f);
            const float e0 = x0 - m, e1 = x1 - m, e2 = x2 - m;
            const float var = fmaf(e0, e0, fmaf(e1, e1, e2 * e2)) * 0.5f; // ddof=1
            local += sqrtf(var) * (1.0f / ((float)Bsz * Npts * (float)C));
        }
    }

    // warp reduce
    #pragma unroll
    for (int off = 16; off > 0; off >>= 1)
        local += __shfl_xor_sync(FULLMASK, local, off);

    __syncthreads();
    if (lane == 0) red[wid] = local;
    __syncthreads();

    if (tid == 0) {
        float s = 0.0f;
        #pragma unroll
        for (int w = 0; w < WARPS; w++) s += red[w];
        atomicAdd(out, s);
    }
}

// ---------------------------------------------------------------------------
extern "C" void kernel_launch(void* const* d_in, const int* in_sizes, int n_in,
                              void* d_out, int out_size)
{
    const float* xyz = (const float*)d_in[0];
    const float* rot = (const float*)d_in[1];
    const float* scl = (const float*)d_in[2];
    const float* col = (const float*)d_in[3];
    const float* opa = (const float*)d_in[4];
    float* out = (float*)d_out;

    prep_kernel<<<NQ / 256, 256>>>(xyz, out);
    knnreg_kernel<<<NQ / QPB, THREADS>>>(xyz, rot, scl, col, opa, out);
}